// round 13
// baseline (speedup 1.0000x reference)
#include <cuda_runtime.h>

// BaseGraphPooling: segment-mean over sorted node_batch.
// node_h: [N,128] fp32, node_batch: [N] int32 sorted, out: [G,128] fp32.
//
// 2 launches (PDL-chained), self-cleaning device scratch:
//  1) chunk_sum : 1184 CTAs dynamically steal 256-row chunks via a global
//                 ticket. PIPELINED steal loop: tickets and smem index
//                 slices are double-buffered, so the next chunk's ticket
//                 ATOMG and index staging latency hide under the current
//                 chunk's streaming. Per chunk: smem bsearch for sub-segment
//                 bounds, 4x-unrolled float4 streaming, red.global.add.v4
//                 into g_scratch + length into g_count.
//  2) divide    : griddepsync, then per-(g,c) scale by 1/max(count,1),
//                 write d_out, re-zero scratch/counters/ticket for replay.

#define NUM_CTAS 1184       // 148 SMs * 8 CTAs/SM, one co-resident wave
#define MAX_G    1024
#define RPC      256        // rows per chunk (full-width staging burst)

__device__ float4       g_scratch[MAX_G * 32];  // zero-init; divide re-zeros
__device__ int          g_count[MAX_G];         // rows per graph
__device__ unsigned int g_ticket = 0;           // chunk dispenser

__device__ __forceinline__ float4 f4add(float4 a, float4 b) {
    a.x += b.x; a.y += b.y; a.z += b.z; a.w += b.w; return a;
}

__device__ __forceinline__ void red_add_v4(float4* addr, float4 v) {
    asm volatile("red.global.add.v4.f32 [%0], {%1, %2, %3, %4};"
                 :: "l"(addr), "f"(v.x), "f"(v.y), "f"(v.z), "f"(v.w)
                 : "memory");
}

__device__ __forceinline__ void red_add_s32(int* addr, int v) {
    asm volatile("red.global.add.s32 [%0], %1;" :: "l"(addr), "r"(v) : "memory");
}

__global__ __launch_bounds__(256, 8)
void chunk_sum_kernel(const float4* __restrict__ h,    // N*32 float4
                      const int* __restrict__ batch,   // N int32, sorted
                      int N, int nchunk) {
    const int tid = threadIdx.x;
    const int c   = tid & 31;   // float4 column (0..31)
    const int r   = tid >> 5;   // row phase (0..7)

    __shared__ float4       smem[256];
    __shared__ int          sb[2][RPC];
    __shared__ unsigned int tkt_s[2];

    // ---- prologue: grab two tickets, stage buffer 0 ----
    if (tid == 0) {
        tkt_s[0] = atomicAdd(&g_ticket, 1u);
        tkt_s[1] = atomicAdd(&g_ticket, 1u);
    }
    __syncthreads();
    {
        const unsigned t0 = tkt_s[0];
        if (t0 < (unsigned)nchunk) {
            const int c0 = (int)t0 * RPC;
            const int len = min(RPC, N - c0);
            if (tid < len) sb[0][tid] = batch[c0 + tid];
        }
    }
    __syncthreads();

    int cur = 0;
    for (;;) {
        const unsigned t = tkt_s[cur];
        if (t >= (unsigned)nchunk) return;

        // ---- stage NEXT chunk's indices early (latency hides under
        //      current chunk's streaming; visibility via loop syncthreads) ----
        const unsigned tn = tkt_s[cur ^ 1];
        if (tn < (unsigned)nchunk) {
            const int cn0 = (int)tn * RPC;
            const int lenn = min(RPC, N - cn0);
            if (tid < lenn) sb[cur ^ 1][tid] = batch[cn0 + tid];
        }

        const int c0 = (int)t * RPC;
        const int c1 = min(c0 + RPC, N);
        const int* __restrict__ sbc = sb[cur];

        int s = c0;
        while (s < c1) {
            const int g = sbc[s - c0];          // current segment id (uniform)
            int lo = s, hi = c1;                // upper_bound via smem bsearch
            while (lo < hi) {
                int mid = (lo + hi) >> 1;
                if (sbc[mid - c0] <= g) lo = mid + 1; else hi = mid;
            }
            const int e = lo;

            float4 a0 = make_float4(0.f, 0.f, 0.f, 0.f);
            float4 a1 = a0, a2 = a0, a3 = a0;

            int i = s + r;
            for (; i + 24 < e; i += 32) {
                float4 v0 = __ldcs(&h[(size_t)(i     ) * 32 + c]);
                float4 v1 = __ldcs(&h[(size_t)(i +  8) * 32 + c]);
                float4 v2 = __ldcs(&h[(size_t)(i + 16) * 32 + c]);
                float4 v3 = __ldcs(&h[(size_t)(i + 24) * 32 + c]);
                a0 = f4add(a0, v0);
                a1 = f4add(a1, v1);
                a2 = f4add(a2, v2);
                a3 = f4add(a3, v3);
            }
            for (; i < e; i += 8)
                a0 = f4add(a0, __ldcs(&h[(size_t)i * 32 + c]));

            smem[tid] = f4add(f4add(a0, a1), f4add(a2, a3));
            __syncthreads();

            if (tid == 0)
                red_add_s32(&g_count[g], e - s);
            if (r == 0) {
                float4 acc = smem[c];
                #pragma unroll
                for (int p = 1; p < 8; p++)
                    acc = f4add(acc, smem[p * 32 + c]);
                red_add_v4(&g_scratch[(size_t)g * 32 + c], acc);
            }
            __syncthreads();                    // smem reuse safety
            s = e;
        }

        // ---- prefetch a fresh ticket into the slot we just finished ----
        if (tid == 0)
            tkt_s[cur] = atomicAdd(&g_ticket, 1u);
        __syncthreads();    // staging of sb[cur^1] + new ticket visible

        cur ^= 1;
    }
}

__global__ void divide_kernel(float4* __restrict__ out, int G) {
    const int idx = blockIdx.x * blockDim.x + threadIdx.x;
    const int g = idx >> 5;
    const int c = idx & 31;

    cudaGridDependencySynchronize();   // primary grid fully complete

    if (idx == 0) g_ticket = 0;        // safe: no chunk_sum thread running

    if (g >= G) return;

    const int cnt = g_count[g];
    const float inv = 1.0f / (float)max(cnt, 1);

    float4 v = g_scratch[(size_t)g * 32 + c];
    // Self-cleaning for the next graph replay.
    g_scratch[(size_t)g * 32 + c] = make_float4(0.f, 0.f, 0.f, 0.f);
    if (c == 0) g_count[g] = 0;

    v.x *= inv; v.y *= inv; v.z *= inv; v.w *= inv;
    out[(size_t)g * 32 + c] = v;
}

extern "C" void kernel_launch(void* const* d_in, const int* in_sizes, int n_in,
                              void* d_out, int out_size) {
    const float4* h     = (const float4*)d_in[0];
    const int*    batch = (const int*)d_in[1];
    const int N = in_sizes[1];       // number of nodes
    const int G = out_size / 128;    // number of graphs

    const int nchunk = (N + RPC - 1) / RPC;
    chunk_sum_kernel<<<NUM_CTAS, 256>>>(h, batch, N, nchunk);

    cudaLaunchAttribute pdl[1];
    pdl[0].id = cudaLaunchAttributeProgrammaticStreamSerialization;
    pdl[0].val.programmaticStreamSerializationAllowed = 1;

    cudaLaunchConfig_t cfg = {};
    cfg.gridDim  = dim3((G * 32 + 255) / 256, 1, 1);
    cfg.blockDim = dim3(256, 1, 1);
    cfg.stream   = 0;
    cfg.attrs    = pdl;
    cfg.numAttrs = 1;
    cudaLaunchKernelEx(&cfg, divide_kernel, (float4*)d_out, G);
}

// round 14
// speedup vs baseline: 1.0147x; 1.0147x over previous
#include <cuda_runtime.h>

// BaseGraphPooling: segment-mean over sorted node_batch.
// node_h: [N,128] fp32, node_batch: [N] int32 sorted, out: [G,128] fp32.
//
// 2 launches (PDL-chained), self-cleaning device scratch:
//  1) chunk_sum : 1184 CTAs greedily steal 128-row chunks via a global
//                 ticket (claim only when ready -> tight drain tail).
//                 Per chunk: stage indices to smem, smem bsearch for
//                 sub-segment bounds, 4x-unrolled float4 streaming,
//                 red.global.add.v4 into g_scratch + length into g_count.
//  2) divide    : griddepsync, then per-(g,c) scale by 1/max(count,1),
//                 write d_out, re-zero scratch/counters/ticket for replay.

#define NUM_CTAS 1184       // 148 SMs * 8 CTAs/SM, one co-resident wave
#define MAX_G    1024
#define RPC      128        // rows per chunk (fine steal granule)

__device__ float4       g_scratch[MAX_G * 32];  // zero-init; divide re-zeros
__device__ int          g_count[MAX_G];         // rows per graph
__device__ unsigned int g_ticket = 0;           // chunk dispenser

__device__ __forceinline__ float4 f4add(float4 a, float4 b) {
    a.x += b.x; a.y += b.y; a.z += b.z; a.w += b.w; return a;
}

__device__ __forceinline__ void red_add_v4(float4* addr, float4 v) {
    asm volatile("red.global.add.v4.f32 [%0], {%1, %2, %3, %4};"
                 :: "l"(addr), "f"(v.x), "f"(v.y), "f"(v.z), "f"(v.w)
                 : "memory");
}

__device__ __forceinline__ void red_add_s32(int* addr, int v) {
    asm volatile("red.global.add.s32 [%0], %1;" :: "l"(addr), "r"(v) : "memory");
}

__global__ __launch_bounds__(256, 8)
void chunk_sum_kernel(const float4* __restrict__ h,    // N*32 float4
                      const int* __restrict__ batch,   // N int32, sorted
                      int N, int nchunk) {
    const int tid = threadIdx.x;
    const int c   = tid & 31;   // float4 column (0..31)
    const int r   = tid >> 5;   // row phase (0..7)

    __shared__ float4       smem[256];
    __shared__ int          sb[RPC];
    __shared__ unsigned int tkt_s;

    for (;;) {
        // ---- grab next chunk (only when ready: tight drain tail) ----
        if (tid == 0)
            tkt_s = atomicAdd(&g_ticket, 1u);
        __syncthreads();
        const unsigned int t = tkt_s;
        __syncthreads();                 // tkt_s reusable next iteration
        if (t >= (unsigned)nchunk) return;

        const int c0 = (int)t * RPC;
        const int c1 = min(c0 + RPC, N);
        const int len = c1 - c0;

        // Stage this chunk's index slice into smem (one coalesced burst).
        if (tid < len)
            sb[tid] = batch[c0 + tid];
        __syncthreads();

        int s = c0;
        while (s < c1) {
            const int g = sb[s - c0];           // current segment id (uniform)
            int lo = s, hi = c1;                // upper_bound via smem bsearch
            while (lo < hi) {
                int mid = (lo + hi) >> 1;
                if (sb[mid - c0] <= g) lo = mid + 1; else hi = mid;
            }
            const int e = lo;

            float4 a0 = make_float4(0.f, 0.f, 0.f, 0.f);
            float4 a1 = a0, a2 = a0, a3 = a0;

            int i = s + r;
            for (; i + 24 < e; i += 32) {
                float4 v0 = __ldcs(&h[(size_t)(i     ) * 32 + c]);
                float4 v1 = __ldcs(&h[(size_t)(i +  8) * 32 + c]);
                float4 v2 = __ldcs(&h[(size_t)(i + 16) * 32 + c]);
                float4 v3 = __ldcs(&h[(size_t)(i + 24) * 32 + c]);
                a0 = f4add(a0, v0);
                a1 = f4add(a1, v1);
                a2 = f4add(a2, v2);
                a3 = f4add(a3, v3);
            }
            for (; i < e; i += 8)
                a0 = f4add(a0, __ldcs(&h[(size_t)i * 32 + c]));

            smem[tid] = f4add(f4add(a0, a1), f4add(a2, a3));
            __syncthreads();

            if (tid == 0)
                red_add_s32(&g_count[g], e - s);
            if (r == 0) {
                float4 acc = smem[c];
                #pragma unroll
                for (int p = 1; p < 8; p++)
                    acc = f4add(acc, smem[p * 32 + c]);
                red_add_v4(&g_scratch[(size_t)g * 32 + c], acc);
            }
            __syncthreads();                    // smem reuse safety
            s = e;
        }
    }
}

__global__ void divide_kernel(float4* __restrict__ out, int G) {
    const int idx = blockIdx.x * blockDim.x + threadIdx.x;
    const int g = idx >> 5;
    const int c = idx & 31;

    cudaGridDependencySynchronize();   // primary grid fully complete

    if (idx == 0) g_ticket = 0;        // safe: no chunk_sum thread running

    if (g >= G) return;

    const int cnt = g_count[g];
    const float inv = 1.0f / (float)max(cnt, 1);

    float4 v = g_scratch[(size_t)g * 32 + c];
    // Self-cleaning for the next graph replay.
    g_scratch[(size_t)g * 32 + c] = make_float4(0.f, 0.f, 0.f, 0.f);
    if (c == 0) g_count[g] = 0;

    v.x *= inv; v.y *= inv; v.z *= inv; v.w *= inv;
    out[(size_t)g * 32 + c] = v;
}

extern "C" void kernel_launch(void* const* d_in, const int* in_sizes, int n_in,
                              void* d_out, int out_size) {
    const float4* h     = (const float4*)d_in[0];
    const int*    batch = (const int*)d_in[1];
    const int N = in_sizes[1];       // number of nodes
    const int G = out_size / 128;    // number of graphs

    const int nchunk = (N + RPC - 1) / RPC;
    chunk_sum_kernel<<<NUM_CTAS, 256>>>(h, batch, N, nchunk);

    cudaLaunchAttribute pdl[1];
    pdl[0].id = cudaLaunchAttributeProgrammaticStreamSerialization;
    pdl[0].val.programmaticStreamSerializationAllowed = 1;

    cudaLaunchConfig_t cfg = {};
    cfg.gridDim  = dim3((G * 32 + 255) / 256, 1, 1);
    cfg.blockDim = dim3(256, 1, 1);
    cfg.stream   = 0;
    cfg.attrs    = pdl;
    cfg.numAttrs = 1;
    cudaLaunchKernelEx(&cfg, divide_kernel, (float4*)d_out, G);
}